// round 1
// baseline (speedup 1.0000x reference)
#include <cuda_runtime.h>

#define B 8
#define O 2048
#define Q 2048
#define D 128

// Scratch (allocation-free rule: device globals)
__device__ __align__(16) float g_P[B * O * D];   // obs_emb @ W^T  (8 MB)
__device__ __align__(16) float g_Wt[D * D];      // W transposed

// ---------------------------------------------------------------------------
// Kernel 0: transpose W (D x D) so later reads are coalesced / row-major in k
// ---------------------------------------------------------------------------
__global__ void k_transpose(const float* __restrict__ W) {
    int idx = blockIdx.x * 256 + threadIdx.x;   // 0 .. 16383
    int e = idx >> 7;
    int d = idx & 127;
    g_Wt[d * D + e] = W[idx];                   // Wt[d][e] = W[e][d]
}

// ---------------------------------------------------------------------------
// Kernel A: P[r][e] = sum_d emb[r][d] * Wt[d][e]   (M=B*O, N=128, K=128)
// Block: 64 rows x 128 cols, 256 threads, 8Mx4N micro-tile, TK=32
// ---------------------------------------------------------------------------
__global__ __launch_bounds__(256) void k_project(const float* __restrict__ emb) {
    __shared__ __align__(16) float As[64 * 32];
    __shared__ __align__(16) float Bs[32 * 128];

    const int tid = threadIdx.x;
    const int tx = tid & 31;        // column group: cols 4*tx .. 4*tx+3
    const int ty = tid >> 5;        // row base: rows ty + 8*j
    const int r0 = blockIdx.x * 64;

    float acc[8][4];
#pragma unroll
    for (int j = 0; j < 8; j++)
#pragma unroll
        for (int n = 0; n < 4; n++) acc[j][n] = 0.0f;

    for (int k0 = 0; k0 < D; k0 += 32) {
        __syncthreads();
        // Load As: 64x32 floats = 512 float4, 2 per thread
#pragma unroll
        for (int i = 0; i < 2; i++) {
            int lin = tid + i * 256;          // float4 index
            int row = lin >> 3;               // 8 float4 per row
            int c4  = lin & 7;
            float4 v = *(const float4*)&emb[(r0 + row) * D + k0 + c4 * 4];
            *(float4*)&As[row * 32 + c4 * 4] = v;
        }
        // Load Bs: 32x128 floats = 1024 float4, 4 per thread
#pragma unroll
        for (int i = 0; i < 4; i++) {
            int lin = tid + i * 256;
            int row = lin >> 5;               // 32 float4 per row
            int c4  = lin & 31;
            float4 v = *(const float4*)&g_Wt[(k0 + row) * D + c4 * 4];
            *(float4*)&Bs[row * 128 + c4 * 4] = v;
        }
        __syncthreads();

#pragma unroll
        for (int kb = 0; kb < 8; kb++) {
            float4 a4[8];
#pragma unroll
            for (int j = 0; j < 8; j++)
                a4[j] = *(const float4*)&As[(ty + 8 * j) * 32 + kb * 4];
#pragma unroll
            for (int r = 0; r < 4; r++) {
                float4 bv = *(const float4*)&Bs[(kb * 4 + r) * 128 + tx * 4];
#pragma unroll
                for (int j = 0; j < 8; j++) {
                    float a = (r == 0) ? a4[j].x : (r == 1) ? a4[j].y
                            : (r == 2) ? a4[j].z : a4[j].w;
                    acc[j][0] += a * bv.x;
                    acc[j][1] += a * bv.y;
                    acc[j][2] += a * bv.z;
                    acc[j][3] += a * bv.w;
                }
            }
        }
    }

#pragma unroll
    for (int j = 0; j < 8; j++) {
        int m = ty + 8 * j;
        float4 v = make_float4(acc[j][0], acc[j][1], acc[j][2], acc[j][3]);
        *(float4*)&g_P[(r0 + m) * D + tx * 4] = v;
    }
}

// ---------------------------------------------------------------------------
// Kernel 1: main fused aggregation.
// For each (b, q-tile of 64): compute RBF weights on the fly into SMEM,
// GEMM against P tiles, track per-row weight sum in registers,
// normalize + add bias in epilogue, write final output.
// ---------------------------------------------------------------------------
__global__ __launch_bounds__(256) void k_agg(
    const float* __restrict__ obs_times,
    const float* __restrict__ query_times,
    const float* __restrict__ obs_mask,
    const float* __restrict__ log_sigma,
    const float* __restrict__ b_proj,
    float* __restrict__ out)
{
    __shared__ __align__(16) float As[64 * 32];   // weights tile
    __shared__ __align__(16) float Ps[32 * 128];  // projected-emb tile
    __shared__ float qt_s[64];
    __shared__ float wsum_s[64];

    const int tid = threadIdx.x;
    const int tx = tid & 31;
    const int ty = tid >> 5;
    const int b  = blockIdx.y;
    const int q0 = blockIdx.x * 64;

    if (tid < 64) qt_s[tid] = query_times[b * Q + q0 + tid];
    __syncthreads();

    // c = -0.5 / sigma^2 ;  sigma = exp(log_sigma)
    const float c = -0.5f * __expf(-2.0f * log_sigma[0]);

    const int wm  = tid >> 2;         // weight-gen row (0..63)
    const int wk0 = (tid & 3) * 8;    // weight-gen k offset in tile
    const float qt = qt_s[wm];

    float acc[8][4];
#pragma unroll
    for (int j = 0; j < 8; j++)
#pragma unroll
        for (int n = 0; n < 4; n++) acc[j][n] = 0.0f;
    float ws = 0.0f;   // partial weight-sum for row wm (this thread's 8 k's)

    for (int k0 = 0; k0 < O; k0 += 32) {
        __syncthreads();
        // Load Ps tile: 32x128 floats = 1024 float4
#pragma unroll
        for (int i = 0; i < 4; i++) {
            int lin = tid + i * 256;
            int row = lin >> 5;
            int c4  = lin & 31;
            float4 v = *(const float4*)&g_P[(b * O + k0 + row) * D + c4 * 4];
            *(float4*)&Ps[row * 128 + c4 * 4] = v;
        }
        // Compute 8 weights (row wm, k = wk0..wk0+7) from global times/mask
        {
            const float4* ot4 = (const float4*)&obs_times[b * O + k0 + wk0];
            const float4* mk4 = (const float4*)&obs_mask[b * O + k0 + wk0];
            float4 t0 = ot4[0], t1 = ot4[1];
            float4 m0 = mk4[0], m1 = mk4[1];
            float w[8];
            float dt;
            dt = qt - t0.x; w[0] = m0.x * __expf(c * dt * dt);
            dt = qt - t0.y; w[1] = m0.y * __expf(c * dt * dt);
            dt = qt - t0.z; w[2] = m0.z * __expf(c * dt * dt);
            dt = qt - t0.w; w[3] = m0.w * __expf(c * dt * dt);
            dt = qt - t1.x; w[4] = m1.x * __expf(c * dt * dt);
            dt = qt - t1.y; w[5] = m1.y * __expf(c * dt * dt);
            dt = qt - t1.z; w[6] = m1.z * __expf(c * dt * dt);
            dt = qt - t1.w; w[7] = m1.w * __expf(c * dt * dt);
            ws += (w[0] + w[1]) + (w[2] + w[3]) + ((w[4] + w[5]) + (w[6] + w[7]));
            *(float4*)&As[wm * 32 + wk0]     = make_float4(w[0], w[1], w[2], w[3]);
            *(float4*)&As[wm * 32 + wk0 + 4] = make_float4(w[4], w[5], w[6], w[7]);
        }
        __syncthreads();

#pragma unroll
        for (int kb = 0; kb < 8; kb++) {
            float4 a4[8];
#pragma unroll
            for (int j = 0; j < 8; j++)
                a4[j] = *(const float4*)&As[(ty + 8 * j) * 32 + kb * 4];
#pragma unroll
            for (int r = 0; r < 4; r++) {
                float4 bv = *(const float4*)&Ps[(kb * 4 + r) * 128 + tx * 4];
#pragma unroll
                for (int j = 0; j < 8; j++) {
                    float a = (r == 0) ? a4[j].x : (r == 1) ? a4[j].y
                            : (r == 2) ? a4[j].z : a4[j].w;
                    acc[j][0] += a * bv.x;
                    acc[j][1] += a * bv.y;
                    acc[j][2] += a * bv.z;
                    acc[j][3] += a * bv.w;
                }
            }
        }
    }

    // Reduce weight sums: 4 threads (lanes tid&3) hold partials for row wm
    ws += __shfl_xor_sync(0xffffffffu, ws, 1);
    ws += __shfl_xor_sync(0xffffffffu, ws, 2);
    if ((tid & 3) == 0) wsum_s[wm] = ws;
    __syncthreads();

    const float4 bb = *(const float4*)&b_proj[tx * 4];
#pragma unroll
    for (int j = 0; j < 8; j++) {
        int m = ty + 8 * j;
        float inv = 1.0f / fmaxf(wsum_s[m], 1e-8f);
        float4 v = make_float4(acc[j][0] * inv + bb.x,
                               acc[j][1] * inv + bb.y,
                               acc[j][2] * inv + bb.z,
                               acc[j][3] * inv + bb.w);
        *(float4*)&out[(b * Q + q0 + m) * D + tx * 4] = v;
    }
}

// ---------------------------------------------------------------------------
extern "C" void kernel_launch(void* const* d_in, const int* in_sizes, int n_in,
                              void* d_out, int out_size) {
    const float* obs_emb     = (const float*)d_in[0];
    const float* obs_times   = (const float*)d_in[1];
    const float* query_times = (const float*)d_in[2];
    const float* obs_mask    = (const float*)d_in[3];
    const float* log_sigma   = (const float*)d_in[4];
    const float* W_proj      = (const float*)d_in[5];
    const float* b_proj      = (const float*)d_in[6];
    float* out = (float*)d_out;

    k_transpose<<<(D * D) / 256, 256>>>(W_proj);
    k_project<<<(B * O) / 64, 256>>>(obs_emb);
    dim3 grid(Q / 64, B);
    k_agg<<<grid, 256>>>(obs_times, query_times, obs_mask, log_sigma,
                         b_proj, out);
}

// round 3
// speedup vs baseline: 2.0002x; 2.0002x over previous
#include <cuda_runtime.h>
#include <cuda_bf16.h>
#include <cstdint>

#define B 8
#define O 2048
#define Q 2048
#define D 128
#define NC 32            // K chunks (O / CK)
#define CK 64            // K per chunk
#define TILE_HALF 16384  // one 128x64 bf16 SW128 tile
#define STAGE 32768      // hi + lo tiles

// Scratch (allocation-free rule: device globals)
__device__ __align__(1024) unsigned char g_Pp[(size_t)B * NC * STAGE]; // 8 MB pre-tiled P hi/lo
__device__ __align__(16) float g_Wt[D * D];

// ============================ PTX helpers ============================
__device__ __forceinline__ uint32_t smem_u32(const void* p) {
    uint32_t a;
    asm("{ .reg .u64 t; cvta.to.shared.u64 t, %1; cvt.u32.u64 %0, t; }" : "=r"(a) : "l"(p));
    return a;
}

#define MBAR_INIT(addr, cnt) \
    asm volatile("mbarrier.init.shared.b64 [%0], %1;" :: "r"(addr), "r"(cnt) : "memory")

#define MBAR_EXPECT_TX(addr, bytes) \
    asm volatile("mbarrier.arrive.expect_tx.shared.b64 _, [%0], %1;" :: "r"(addr), "r"(bytes) : "memory")

#define MBAR_WAIT(mbar, parity) do { \
    uint32_t _m = (mbar); uint32_t _p = (parity); uint32_t _done; \
    asm volatile("{\n\t.reg .pred p;\n\t" \
        "mbarrier.try_wait.parity.acquire.cta.shared::cta.b64 p, [%1], %2;\n\t" \
        "selp.b32 %0, 1, 0, p;\n\t}" : "=r"(_done) : "r"(_m), "r"(_p) : "memory"); \
    if (!_done) { \
        asm volatile("{\n\t.reg .pred P1;\n\t" \
            "WL%=:\n\t" \
            "mbarrier.try_wait.parity.acquire.cta.shared::cta.b64 P1, [%0], %1, 0x989680;\n\t" \
            "@P1 bra.uni WD%=;\n\t" \
            "bra.uni WL%=;\n\t" \
            "WD%=:\n\t}" :: "r"(_m), "r"(_p) : "memory"); \
    } \
} while (0)

#define BULK_G2S(dst, src, bytes, mbar) \
    asm volatile("cp.async.bulk.shared::cta.global.mbarrier::complete_tx::bytes [%0], [%1], %2, [%3];" \
        :: "r"(dst), "l"(src), "r"(bytes), "r"(mbar) : "memory")

#define LDSM_X4(r0, r1, r2, r3, addr) \
    asm volatile("ldmatrix.sync.aligned.m8n8.x4.shared.b16 {%0,%1,%2,%3}, [%4];" \
        : "=r"(r0), "=r"(r1), "=r"(r2), "=r"(r3) : "r"(addr))

#define MMA16816(d, a0, a1, a2, a3, b0, b1) \
    asm volatile("mma.sync.aligned.m16n8k16.row.col.f32.bf16.bf16.f32 " \
        "{%0,%1,%2,%3}, {%4,%5,%6,%7}, {%8,%9}, {%0,%1,%2,%3};" \
        : "+f"((d)[0]), "+f"((d)[1]), "+f"((d)[2]), "+f"((d)[3]) \
        : "r"(a0), "r"(a1), "r"(a2), "r"(a3), "r"(b0), "r"(b1))

// ---------------------------------------------------------------------------
// Kernel 0: transpose W (D x D)
// ---------------------------------------------------------------------------
__global__ void k_transpose(const float* __restrict__ W) {
    int idx = blockIdx.x * 256 + threadIdx.x;
    int e = idx >> 7;
    int d = idx & 127;
    g_Wt[d * D + e] = W[idx];
}

// ---------------------------------------------------------------------------
// Kernel A: P = emb @ W^T, split to bf16 hi/lo, write pre-tiled pre-swizzled
// 32KB blocks: g_Pp[b*32+chunk] = [hi 16KB][lo 16KB], row e (dim), 128B rows,
// byte_off = e*128 + kc*2, SW128-swizzled. One block = one (b, 64-obs chunk).
// ---------------------------------------------------------------------------
__global__ __launch_bounds__(256) void k_project(const float* __restrict__ emb) {
    __shared__ __align__(16) unsigned char buf[32768];
    float* As = (float*)buf;              // 64x32 fp32
    float* Bs = (float*)(buf + 8192);     // 32x128 fp32

    const int tid = threadIdx.x;
    const int tx = tid & 31;
    const int ty = tid >> 5;
    const int r0 = blockIdx.x * 64;

    float acc[8][4];
#pragma unroll
    for (int j = 0; j < 8; j++)
#pragma unroll
        for (int n = 0; n < 4; n++) acc[j][n] = 0.0f;

    for (int k0 = 0; k0 < D; k0 += 32) {
        __syncthreads();
#pragma unroll
        for (int i = 0; i < 2; i++) {
            int lin = tid + i * 256;
            int row = lin >> 3;
            int c4  = lin & 7;
            float4 v = *(const float4*)&emb[(r0 + row) * D + k0 + c4 * 4];
            *(float4*)&As[row * 32 + c4 * 4] = v;
        }
#pragma unroll
        for (int i = 0; i < 4; i++) {
            int lin = tid + i * 256;
            int row = lin >> 5;
            int c4  = lin & 31;
            float4 v = *(const float4*)&g_Wt[(k0 + row) * D + c4 * 4];
            *(float4*)&Bs[row * 128 + c4 * 4] = v;
        }
        __syncthreads();

#pragma unroll
        for (int kb = 0; kb < 8; kb++) {
            float4 a4[8];
#pragma unroll
            for (int j = 0; j < 8; j++)
                a4[j] = *(const float4*)&As[(ty + 8 * j) * 32 + kb * 4];
#pragma unroll
            for (int r = 0; r < 4; r++) {
                float4 bv = *(const float4*)&Bs[(kb * 4 + r) * 128 + tx * 4];
#pragma unroll
                for (int j = 0; j < 8; j++) {
                    float a = (r == 0) ? a4[j].x : (r == 1) ? a4[j].y
                            : (r == 2) ? a4[j].z : a4[j].w;
                    acc[j][0] += a * bv.x;
                    acc[j][1] += a * bv.y;
                    acc[j][2] += a * bv.z;
                    acc[j][3] += a * bv.w;
                }
            }
        }
    }
    __syncthreads();

    // Stage bf16 hi/lo UNSWIZZLED: s[e*64 + kc]
    __nv_bfloat16* s_hi = (__nv_bfloat16*)buf;
    __nv_bfloat16* s_lo = (__nv_bfloat16*)(buf + TILE_HALF);
#pragma unroll
    for (int j = 0; j < 8; j++) {
        int kc = ty + 8 * j;
#pragma unroll
        for (int n = 0; n < 4; n++) {
            int e = tx * 4 + n;
            float v = acc[j][n];
            __nv_bfloat16 h = __float2bfloat16(v);
            s_hi[e * 64 + kc] = h;
            s_lo[e * 64 + kc] = __float2bfloat16(v - __bfloat162float(h));
        }
    }
    __syncthreads();

    // Coalesced swizzled write-out (sw128 is an involution)
    unsigned char* dst = g_Pp + (size_t)blockIdx.x * STAGE;
#pragma unroll
    for (int i = 0; i < 4; i++) {
        int g = (tid + i * 256) * 16;
        int sg = g ^ ((g >> 3) & 0x70);
        *(uint4*)(dst + g)             = *(const uint4*)(buf + sg);
        *(uint4*)(dst + TILE_HALF + g) = *(const uint4*)(buf + TILE_HALF + sg);
    }
}

// ---------------------------------------------------------------------------
// Kernel 1: fused RBF-weight GEMM on mma.sync bf16 (split-bf16 x3).
// One CTA = 128 q-rows x 128 dims, K = 2048 in 32 chunks of 64.
// ---------------------------------------------------------------------------
#define SM_A     0u        // 2 stages x 32KB (hi+lo weight tiles)
#define SM_B     65536u    // 2 stages x 32KB (hi+lo P tiles)
#define SM_WSUM  131072u   // 128 floats
#define SM_BF    131584u   // 2 mbarriers
#define SMEM_TOTAL 131712

struct WPack { uint2 h[8]; uint2 l[8]; };

// Compute 32 weights (row m, k offsets koff..koff+31 of chunk c) into packed
// bf16 hi/lo; returns the fp32 partial sum.
__device__ __forceinline__ float gen_chunk(const float* __restrict__ otp,
                                           const float* __restrict__ mkp,
                                           float qt, float cc, WPack& wp) {
    float ws = 0.0f;
#pragma unroll
    for (int j = 0; j < 8; ++j) {
        float4 t4 = *(const float4*)(otp + j * 4);
        float4 m4 = *(const float4*)(mkp + j * 4);
        float d0 = qt - t4.x, d1 = qt - t4.y, d2 = qt - t4.z, d3 = qt - t4.w;
        float w0 = m4.x * __expf(cc * d0 * d0);
        float w1 = m4.y * __expf(cc * d1 * d1);
        float w2 = m4.z * __expf(cc * d2 * d2);
        float w3 = m4.w * __expf(cc * d3 * d3);
        ws += (w0 + w1) + (w2 + w3);
        uint32_t h01, h23, l01, l23;
        asm("cvt.rn.satfinite.bf16x2.f32 %0, %1, %2;" : "=r"(h01) : "f"(w1), "f"(w0));
        asm("cvt.rn.satfinite.bf16x2.f32 %0, %1, %2;" : "=r"(h23) : "f"(w3), "f"(w2));
        float r0 = w0 - __uint_as_float(h01 << 16);
        float r1 = w1 - __uint_as_float(h01 & 0xffff0000u);
        float r2 = w2 - __uint_as_float(h23 << 16);
        float r3 = w3 - __uint_as_float(h23 & 0xffff0000u);
        asm("cvt.rn.satfinite.bf16x2.f32 %0, %1, %2;" : "=r"(l01) : "f"(r1), "f"(r0));
        asm("cvt.rn.satfinite.bf16x2.f32 %0, %1, %2;" : "=r"(l23) : "f"(r3), "f"(r2));
        wp.h[j] = make_uint2(h01, h23);
        wp.l[j] = make_uint2(l01, l23);
    }
    return ws;
}

__device__ __forceinline__ void sts_chunk(unsigned char* aHi, const WPack& wp,
                                          int m, int koff) {
    unsigned char* aLo = aHi + TILE_HALF;
    const int rb = m * 128 + koff * 2;
#pragma unroll
    for (int j = 0; j < 8; ++j) {
        int off = rb + j * 8;
        int so  = off ^ ((off >> 3) & 0x70);   // SW128
        *(uint2*)(aHi + so) = wp.h[j];
        *(uint2*)(aLo + so) = wp.l[j];
    }
}

__global__ __launch_bounds__(256)
void k_agg(const float* __restrict__ obs_times,
           const float* __restrict__ query_times,
           const float* __restrict__ obs_mask,
           const float* __restrict__ log_sigma,
           const float* __restrict__ b_proj,
           float* __restrict__ out)
{
    extern __shared__ __align__(1024) unsigned char smem[];
    const uint32_t sb = smem_u32(smem);
    const int tid = threadIdx.x;
    const int wid = tid >> 5;
    const int lid = tid & 31;
    const int b   = blockIdx.y;
    const int q0  = blockIdx.x * 128;
    float* wsum = (float*)(smem + SM_WSUM);

    if (tid == 0) {
        MBAR_INIT(sb + SM_BF + 0, 1);
        MBAR_INIT(sb + SM_BF + 8, 1);
    }
    __syncthreads();

    const unsigned char* psrc = g_Pp + (size_t)b * NC * STAGE;
    if (tid == 0) {
        MBAR_EXPECT_TX(sb + SM_BF + 0, STAGE);
        BULK_G2S(sb + SM_B + 0 * STAGE, psrc + (size_t)0 * STAGE, STAGE, sb + SM_BF + 0);
        MBAR_EXPECT_TX(sb + SM_BF + 8, STAGE);
        BULK_G2S(sb + SM_B + 1 * STAGE, psrc + (size_t)1 * STAGE, STAGE, sb + SM_BF + 8);
    }

    const float cc = -0.5f * __expf(-2.0f * log_sigma[0]);
    const int m    = tid >> 1;          // weight-gen row (0..127)
    const int koff = (tid & 1) * 32;    // k offset within chunk
    const float qt = query_times[b * Q + q0 + m];
    const float* otb = obs_times + b * O + koff;
    const float* mkb = obs_mask  + b * O + koff;

    // Prologue: weights for chunk 0
    float ws = 0.0f;
    {
        WPack wp;
        ws += gen_chunk(otb, mkb, qt, cc, wp);
        sts_chunk(smem + SM_A, wp, m, koff);
    }
    __syncthreads();

    // --- warp / lane fragment addressing (SW128) ---
    const int wm = wid & 3;             // m-warp (32 rows)
    const int wn = wid >> 2;            // n-warp (64 cols)
    const int m0 = wm * 32;
    const int n0 = wn * 64;
    // A: row = m0 + mi*16 + (lid&15); kbyte = ks*32 + (lid>>4)*16
    const int arow = m0 + (lid & 15);
    const uint32_t a_fix = (uint32_t)arow * 128;
    const uint32_t a_x   = (uint32_t)(arow & 7) << 4;
    const uint32_t a_k   = (uint32_t)(lid >> 4) * 16;
    // B: row = n0 + ((lid>>4)<<3) + (lid&7); kbyte = ks*32 + ((lid>>3)&1)*16
    const int brow = n0 + ((lid >> 4) << 3) + (lid & 7);
    const uint32_t b_fix = (uint32_t)brow * 128;
    const uint32_t b_x   = (uint32_t)(brow & 7) << 4;
    const uint32_t b_k   = (uint32_t)((lid >> 3) & 1) * 16;

    float acc[2][8][4];
#pragma unroll
    for (int mi = 0; mi < 2; mi++)
#pragma unroll
        for (int j = 0; j < 8; j++)
#pragma unroll
            for (int t = 0; t < 4; t++) acc[mi][j][t] = 0.0f;

    for (int c = 0; c < NC; ++c) {
        const int s = c & 1;
        MBAR_WAIT(sb + SM_BF + s * 8, (c >> 1) & 1);

        const uint32_t aB = sb + SM_A + (uint32_t)s * STAGE;
        const uint32_t bB = sb + SM_B + (uint32_t)s * STAGE;

#pragma unroll
        for (int ks = 0; ks < 4; ++ks) {
            const uint32_t ak = ((uint32_t)(ks * 32) + a_k) ^ a_x;
            const uint32_t bk = ((uint32_t)(ks * 32) + b_k) ^ b_x;
            uint32_t ah[2][4], al[2][4];
#pragma unroll
            for (int mi = 0; mi < 2; ++mi) {
                uint32_t ad = aB + a_fix + (uint32_t)mi * 2048 + ak;
                LDSM_X4(ah[mi][0], ah[mi][1], ah[mi][2], ah[mi][3], ad);
                LDSM_X4(al[mi][0], al[mi][1], al[mi][2], al[mi][3], ad + TILE_HALF);
            }
            uint32_t bh[4][4], bl[4][4];
#pragma unroll
            for (int nt = 0; nt < 4; ++nt) {
                uint32_t bd = bB + b_fix + (uint32_t)nt * 2048 + bk;
                LDSM_X4(bh[nt][0], bh[nt][1], bh[nt][2], bh[nt][3], bd);
                LDSM_X4(bl[nt][0], bl[nt][1], bl[nt][2], bl[nt][3], bd + TILE_HALF);
            }
#pragma unroll
            for (int mi = 0; mi < 2; ++mi)
#pragma unroll
                for (int nt = 0; nt < 4; ++nt)
#pragma unroll
                    for (int h2 = 0; h2 < 2; ++h2) {
                        const int j = nt * 2 + h2;
                        const int r0i = h2 * 2, r1i = h2 * 2 + 1;
                        MMA16816(acc[mi][j], ah[mi][0], ah[mi][1], ah[mi][2], ah[mi][3],
                                 bh[nt][r0i], bh[nt][r1i]);
                        MMA16816(acc[mi][j], al[mi][0], al[mi][1], al[mi][2], al[mi][3],
                                 bh[nt][r0i], bh[nt][r1i]);
                        MMA16816(acc[mi][j], ah[mi][0], ah[mi][1], ah[mi][2], ah[mi][3],
                                 bl[nt][r0i], bl[nt][r1i]);
                    }
        }

        // Weight generation for chunk c+1 (interleaves with HMMA above)
        if (c + 1 < NC) {
            WPack wp;
            ws += gen_chunk(otb + (c + 1) * CK, mkb + (c + 1) * CK, qt, cc, wp);
            sts_chunk(smem + SM_A + (s ^ 1) * STAGE, wp, m, koff);
        }
        __syncthreads();
        if (tid == 0 && c + 2 < NC) {
            MBAR_EXPECT_TX(sb + SM_BF + s * 8, STAGE);
            BULK_G2S(sb + SM_B + (uint32_t)s * STAGE,
                     psrc + (size_t)(c + 2) * STAGE, STAGE, sb + SM_BF + s * 8);
        }
    }

    // ---- weight-sum reduce (pairs of threads share a row) ----
    float wo = __shfl_xor_sync(0xffffffffu, ws, 1);
    if ((tid & 1) == 0) wsum[m] = ws + wo;
    __syncthreads();

    // ---- epilogue: normalize + bias + store ----
    {
        const int g = lid >> 2, t = lid & 3;
#pragma unroll
        for (int mi = 0; mi < 2; ++mi) {
            const int r1 = m0 + mi * 16 + g;
            const int r2 = r1 + 8;
            const float inv1 = 1.0f / fmaxf(wsum[r1], 1e-8f);
            const float inv2 = 1.0f / fmaxf(wsum[r2], 1e-8f);
            float* o1 = out + ((size_t)(b * Q) + q0 + r1) * D + n0;
            float* o2 = out + ((size_t)(b * Q) + q0 + r2) * D + n0;
#pragma unroll
            for (int j = 0; j < 8; ++j) {
                const int col = j * 8 + t * 2;
                float2 bb = *(const float2*)&b_proj[n0 + col];
                float2 v1, v2;
                v1.x = acc[mi][j][0] * inv1 + bb.x;
                v1.y = acc[mi][j][1] * inv1 + bb.y;
                v2.x = acc[mi][j][2] * inv2 + bb.x;
                v2.y = acc[mi][j][3] * inv2 + bb.y;
                *(float2*)(o1 + col) = v1;
                *(float2*)(o2 + col) = v2;
            }
        }
    }
}

// ---------------------------------------------------------------------------
extern "C" void kernel_launch(void* const* d_in, const int* in_sizes, int n_in,
                              void* d_out, int out_size) {
    const float* obs_emb     = (const float*)d_in[0];
    const float* obs_times   = (const float*)d_in[1];
    const float* query_times = (const float*)d_in[2];
    const float* obs_mask    = (const float*)d_in[3];
    const float* log_sigma   = (const float*)d_in[4];
    const float* W_proj      = (const float*)d_in[5];
    const float* b_proj      = (const float*)d_in[6];
    float* out = (float*)d_out;

    cudaFuncSetAttribute(k_agg, cudaFuncAttributeMaxDynamicSharedMemorySize, SMEM_TOTAL);

    k_transpose<<<(D * D) / 256, 256>>>(W_proj);
    k_project<<<(B * O) / 64, 256>>>(obs_emb);
    dim3 grid(Q / 128, B);
    k_agg<<<grid, 256, SMEM_TOTAL>>>(obs_times, query_times, obs_mask, log_sigma,
                                     b_proj, out);
}

// round 4
// speedup vs baseline: 10.3447x; 5.1717x over previous
#include <cuda_runtime.h>
#include <cstdint>

#define B 8
#define O 2048
#define Q 2048
#define D 128
#define KT 13      // expansion terms k = 0..12
#define NCH 16     // obs chunks per batch
#define CH 128     // obs rows per chunk

// Scratch (allocation-free rule: device globals)
__device__ __align__(16) float g_Mpart[B * NCH * KT * D];  // per-chunk moment partials
__device__ __align__(16) float g_mspart[B * NCH * KT];     // per-chunk weight-sum partials
__device__ __align__(16) float g_Mp[B * KT * D];           // projected moments
__device__ __align__(16) float g_msum[B * KT];             // weight-sum moments

__constant__ float c_invk[KT] = {0.f, 1.f, 1.f/2, 1.f/3, 1.f/4, 1.f/5, 1.f/6,
                                 1.f/7, 1.f/8, 1.f/9, 1.f/10, 1.f/11, 1.f/12};

// ---------------------------------------------------------------------------
// Kernel A: per (batch, 128-obs chunk) moment partials.
//   g_k(o) = mask_o * exp(-0.5*c2*t_o^2) * (c2*t_o)^k / k!
//   Mpart[k][e] = sum_o g_k(o) * emb[o][e] ;  mspart[k] = sum_o g_k(o)
// ---------------------------------------------------------------------------
__global__ __launch_bounds__(256) void k_moments(
    const float* __restrict__ obs_emb,
    const float* __restrict__ obs_times,
    const float* __restrict__ obs_mask,
    const float* __restrict__ log_sigma)
{
    __shared__ __align__(16) float g_s[CH * 16];   // 13 used, padded to 16
    __shared__ __align__(16) float red[KT * D];

    const int tid = threadIdx.x;
    const int c   = blockIdx.x;
    const int b   = blockIdx.y;
    const int o0  = c * CH;
    const float c2 = expf(-2.0f * log_sigma[0]);   // 1/sigma^2

    // Phase 1: 128 threads compute g_k rows
    if (tid < CH) {
        const int o = o0 + tid;
        const float t  = obs_times[b * O + o];
        const float mk = obs_mask[b * O + o];
        const float x  = c2 * t;
        float g = mk * __expf(-0.5f * c2 * t * t);
        g_s[tid * 16 + 0] = g;
#pragma unroll
        for (int k = 1; k < KT; ++k) {
            g *= x * c_invk[k];
            g_s[tid * 16 + k] = g;
        }
    }
    __syncthreads();

    // ms partials (tiny)
    if (tid < KT) {
        float s = 0.0f;
        for (int o = 0; o < CH; ++o) s += g_s[o * 16 + tid];
        g_mspart[(b * NCH + c) * KT + tid] = s;
    }

    // Phase 2: accumulate moments. e = tid&127, half = tid>>7 handles 64 rows.
    const int e    = tid & 127;
    const int half = tid >> 7;
    float acc[KT];
#pragma unroll
    for (int k = 0; k < KT; ++k) acc[k] = 0.0f;

    const float* ebase = obs_emb + ((size_t)(b * O) + o0 + half * 64) * D + e;
    const float* gbase = g_s + half * 64 * 16;
#pragma unroll 4
    for (int oo = 0; oo < 64; ++oo) {
        const float x = ebase[(size_t)oo * D];
        const float4 ga = *(const float4*)(gbase + oo * 16 + 0);
        const float4 gb = *(const float4*)(gbase + oo * 16 + 4);
        const float4 gc = *(const float4*)(gbase + oo * 16 + 8);
        const float  gd = gbase[oo * 16 + 12];
        acc[0] += ga.x * x;  acc[1] += ga.y * x;  acc[2] += ga.z * x;  acc[3] += ga.w * x;
        acc[4] += gb.x * x;  acc[5] += gb.y * x;  acc[6] += gb.z * x;  acc[7] += gb.w * x;
        acc[8] += gc.x * x;  acc[9] += gc.y * x;  acc[10] += gc.z * x; acc[11] += gc.w * x;
        acc[12] += gd * x;
    }

    // combine the two halves via SMEM
    if (half == 1) {
#pragma unroll
        for (int k = 0; k < KT; ++k) red[k * D + e] = acc[k];
    }
    __syncthreads();
    if (half == 0) {
        float* dst = g_Mpart + (size_t)((b * NCH + c) * KT) * D;
#pragma unroll
        for (int k = 0; k < KT; ++k) dst[k * D + e] = acc[k] + red[k * D + e];
    }
}

// ---------------------------------------------------------------------------
// Kernel B: reduce chunk partials and project through W.
//   M[e] = sum_c Mpart ;  Mp[b][k][e'] = sum_e W[e'][e] * M[e]
//   msum[b][k] = sum_c mspart
// One CTA per (b, k), 128 threads.
// ---------------------------------------------------------------------------
__global__ __launch_bounds__(128) void k_reduce_project(
    const float* __restrict__ W_proj)
{
    __shared__ __align__(16) float m_s[D];
    const int tid = threadIdx.x;
    const int k = blockIdx.x % KT;
    const int b = blockIdx.x / KT;

    float s = 0.0f;
    for (int c = 0; c < NCH; ++c)
        s += g_Mpart[(size_t)((b * NCH + c) * KT + k) * D + tid];
    m_s[tid] = s;

    if (tid == 0) {
        float ms = 0.0f;
        for (int c = 0; c < NCH; ++c)
            ms += g_mspart[(b * NCH + c) * KT + k];
        g_msum[b * KT + k] = ms;
    }
    __syncthreads();

    // thread tid = output dim e': dot(W[e'][:], m)
    const float4* wrow = (const float4*)(W_proj + (size_t)tid * D);
    float dot = 0.0f;
#pragma unroll
    for (int i = 0; i < D / 4; ++i) {
        float4 w4 = wrow[i];
        const float4 m4 = *(const float4*)&m_s[i * 4];
        dot += w4.x * m4.x + w4.y * m4.y + w4.z * m4.z + w4.w * m4.w;
    }
    g_Mp[(size_t)(b * KT + k) * D + tid] = dot;
}

// ---------------------------------------------------------------------------
// Kernel C: combine.  out[q][e'] = (sum_k f_k(q) Mp[k][e']) / (sum_k f_k msum[k]) + b[e']
//   f_k(q) = exp(-0.5*c2*qt^2) * qt^k
// CTA = 32 q rows, 256 threads (2 q-groups x 128 dims), 16 q per thread.
// ---------------------------------------------------------------------------
__global__ __launch_bounds__(256) void k_combine(
    const float* __restrict__ query_times,
    const float* __restrict__ log_sigma,
    const float* __restrict__ b_proj,
    float* __restrict__ out)
{
    __shared__ __align__(16) float mp_s[KT * D];
    __shared__ float ms_s[KT];

    const int tid = threadIdx.x;
    const int b   = blockIdx.y;
    const int q0  = blockIdx.x * 32;

    for (int i = tid; i < KT * D; i += 256)
        mp_s[i] = g_Mp[(size_t)b * KT * D + i];
    if (tid < KT) ms_s[tid] = g_msum[b * KT + tid];
    __syncthreads();

    const float c2 = expf(-2.0f * log_sigma[0]);
    const int e  = tid & 127;
    const int qh = tid >> 7;
    const float bp = b_proj[e];

#pragma unroll 2
    for (int i = 0; i < 16; ++i) {
        const int q = q0 + qh * 16 + i;
        const float qt = query_times[b * Q + q];
        float f = __expf(-0.5f * c2 * qt * qt);
        float num = f * mp_s[e];
        float den = f * ms_s[0];
#pragma unroll
        for (int k = 1; k < KT; ++k) {
            f *= qt;
            num += f * mp_s[k * D + e];
            den += f * ms_s[k];
        }
        out[((size_t)(b * Q) + q) * D + e] = num / fmaxf(den, 1e-8f) + bp;
    }
}

// ---------------------------------------------------------------------------
extern "C" void kernel_launch(void* const* d_in, const int* in_sizes, int n_in,
                              void* d_out, int out_size) {
    const float* obs_emb     = (const float*)d_in[0];
    const float* obs_times   = (const float*)d_in[1];
    const float* query_times = (const float*)d_in[2];
    const float* obs_mask    = (const float*)d_in[3];
    const float* log_sigma   = (const float*)d_in[4];
    const float* W_proj      = (const float*)d_in[5];
    const float* b_proj      = (const float*)d_in[6];
    float* out = (float*)d_out;

    dim3 gA(NCH, B);
    k_moments<<<gA, 256>>>(obs_emb, obs_times, obs_mask, log_sigma);
    k_reduce_project<<<B * KT, 128>>>(W_proj);
    dim3 gC(Q / 32, B);
    k_combine<<<gC, 256>>>(query_times, log_sigma, b_proj, out);
}

// round 5
// speedup vs baseline: 10.3578x; 1.0013x over previous
#include <cuda_runtime.h>
#include <cstdint>

#define B 8
#define O 2048
#define Q 2048
#define D 128
#define KT 13      // expansion terms k = 0..12
#define NCH 64     // obs chunks per batch
#define CH 32      // obs rows per chunk

// Scratch (allocation-free rule: device globals)
__device__ __align__(16) float g_Mpart[B * NCH * KT * D];  // per-chunk moment partials
__device__ __align__(16) float g_mspart[B * NCH * KT];     // per-chunk weight-sum partials
__device__ __align__(16) float g_Mp[B * KT * D];           // projected moments
__device__ __align__(16) float g_msum[B * KT];             // weight-sum moments

__constant__ float c_invk[KT] = {0.f, 1.f, 1.f/2, 1.f/3, 1.f/4, 1.f/5, 1.f/6,
                                 1.f/7, 1.f/8, 1.f/9, 1.f/10, 1.f/11, 1.f/12};

// ---------------------------------------------------------------------------
// Kernel A: per (batch, 32-obs chunk) moment partials.
//   g_k(o) = mask_o * exp(-0.5*c2*t_o^2) * (c2*t_o)^k / k!
//   Mpart[k][e] = sum_o g_k(o) * emb[o][e] ;  mspart[k] = sum_o g_k(o)
// grid (64, 8) = 512 CTAs, 256 threads: e = tid&127, half = tid>>7 (16 rows).
// ---------------------------------------------------------------------------
__global__ __launch_bounds__(256) void k_moments(
    const float* __restrict__ obs_emb,
    const float* __restrict__ obs_times,
    const float* __restrict__ obs_mask,
    const float* __restrict__ log_sigma)
{
    __shared__ __align__(16) float g_s[CH * 16];   // 13 used, padded to 16
    __shared__ __align__(16) float red[KT * D];

    const int tid = threadIdx.x;
    const int c   = blockIdx.x;
    const int b   = blockIdx.y;
    const int o0  = c * CH;
    const float c2 = expf(-2.0f * log_sigma[0]);   // 1/sigma^2

    // Phase 1: 32 threads compute g_k rows
    if (tid < CH) {
        const int o = o0 + tid;
        const float t  = obs_times[b * O + o];
        const float mk = obs_mask[b * O + o];
        const float x  = c2 * t;
        float g = mk * __expf(-0.5f * c2 * t * t);
        g_s[tid * 16 + 0] = g;
#pragma unroll
        for (int k = 1; k < KT; ++k) {
            g *= x * c_invk[k];
            g_s[tid * 16 + k] = g;
        }
    }
    __syncthreads();

    // ms partials (tiny)
    if (tid < KT) {
        float s = 0.0f;
#pragma unroll
        for (int o = 0; o < CH; ++o) s += g_s[o * 16 + tid];
        g_mspart[(b * NCH + c) * KT + tid] = s;
    }

    // Phase 2: accumulate moments over 16 rows per thread.
    const int e    = tid & 127;
    const int half = tid >> 7;
    float acc[KT];
#pragma unroll
    for (int k = 0; k < KT; ++k) acc[k] = 0.0f;

    const float* ebase = obs_emb + ((size_t)(b * O) + o0 + half * 16) * D + e;
    const float* gbase = g_s + half * 16 * 16;
#pragma unroll
    for (int oo = 0; oo < 16; ++oo) {
        const float x = ebase[(size_t)oo * D];
        const float4 ga = *(const float4*)(gbase + oo * 16 + 0);
        const float4 gb = *(const float4*)(gbase + oo * 16 + 4);
        const float4 gc = *(const float4*)(gbase + oo * 16 + 8);
        const float  gd = gbase[oo * 16 + 12];
        acc[0] += ga.x * x;  acc[1] += ga.y * x;  acc[2] += ga.z * x;  acc[3] += ga.w * x;
        acc[4] += gb.x * x;  acc[5] += gb.y * x;  acc[6] += gb.z * x;  acc[7] += gb.w * x;
        acc[8] += gc.x * x;  acc[9] += gc.y * x;  acc[10] += gc.z * x; acc[11] += gc.w * x;
        acc[12] += gd * x;
    }

    // combine the two halves via SMEM
    if (half == 1) {
#pragma unroll
        for (int k = 0; k < KT; ++k) red[k * D + e] = acc[k];
    }
    __syncthreads();
    if (half == 0) {
        float* dst = g_Mpart + (size_t)((b * NCH + c) * KT) * D;
#pragma unroll
        for (int k = 0; k < KT; ++k) dst[k * D + e] = acc[k] + red[k * D + e];
    }
}

// ---------------------------------------------------------------------------
// Kernel B: reduce chunk partials and project through W.
//   M[e] = sum_c Mpart ;  Mp[b][k][e'] = sum_e W[e'][e] * M[e]
// One CTA per (b, k), 256 threads: c-sum split across 2 thread halves.
// ---------------------------------------------------------------------------
__global__ __launch_bounds__(256) void k_reduce_project(
    const float* __restrict__ W_proj)
{
    __shared__ __align__(16) float m_s[D];
    __shared__ __align__(16) float red[D];
    const int tid = threadIdx.x;
    const int e   = tid & 127;
    const int h   = tid >> 7;
    const int k = blockIdx.x % KT;
    const int b = blockIdx.x / KT;

    float s = 0.0f;
#pragma unroll 8
    for (int c = h * (NCH / 2); c < (h + 1) * (NCH / 2); ++c)
        s += g_Mpart[(size_t)((b * NCH + c) * KT + k) * D + e];
    if (h == 1) red[e] = s;

    if (tid == 0) {
        float ms = 0.0f;
#pragma unroll 8
        for (int c = 0; c < NCH; ++c)
            ms += g_mspart[(b * NCH + c) * KT + k];
        g_msum[b * KT + k] = ms;
    }
    __syncthreads();
    if (h == 0) m_s[e] = s + red[e];
    __syncthreads();

    if (h == 0) {
        // thread e = output dim: dot(W[e][:], m)
        const float4* wrow = (const float4*)(W_proj + (size_t)e * D);
        float dot = 0.0f;
#pragma unroll
        for (int i = 0; i < D / 4; ++i) {
            float4 w4 = wrow[i];
            const float4 m4 = *(const float4*)&m_s[i * 4];
            dot += w4.x * m4.x + w4.y * m4.y + w4.z * m4.z + w4.w * m4.w;
        }
        g_Mp[(size_t)(b * KT + k) * D + e] = dot;
    }
}

// ---------------------------------------------------------------------------
// Kernel C: combine.  out[q][e'] = (sum_k f_k(q) Mp[k][e']) / (sum_k f_k msum[k]) + b[e']
//   f_k(q) = exp(-0.5*c2*qt^2) * qt^k
// Mp[k][e] and msum[k] live in REGISTERS (e fixed per thread) — inner loop is
// pure FMA. CTA = 32 q rows, 256 threads (2 q-halves x 128 dims), 16 q/thread.
// ---------------------------------------------------------------------------
__global__ __launch_bounds__(256) void k_combine(
    const float* __restrict__ query_times,
    const float* __restrict__ log_sigma,
    const float* __restrict__ b_proj,
    float* __restrict__ out)
{
    const int tid = threadIdx.x;
    const int b   = blockIdx.y;
    const int q0  = blockIdx.x * 32;
    const int e   = tid & 127;
    const int qh  = tid >> 7;

    float mp[KT], ms[KT];
    const float* mpb = g_Mp + (size_t)b * KT * D + e;
    const float* msb = g_msum + b * KT;
#pragma unroll
    for (int k = 0; k < KT; ++k) {
        mp[k] = mpb[k * D];
        ms[k] = msb[k];
    }

    const float c2 = expf(-2.0f * log_sigma[0]);
    const float bp = b_proj[e];
    const float* qtp = query_times + b * Q + q0 + qh * 16;
    float* ob = out + ((size_t)(b * Q) + q0 + qh * 16) * D + e;

#pragma unroll 4
    for (int i = 0; i < 16; ++i) {
        const float qt = qtp[i];
        float f = __expf(-0.5f * c2 * qt * qt);
        float num = f * mp[0];
        float den = f * ms[0];
#pragma unroll
        for (int k = 1; k < KT; ++k) {
            f *= qt;
            num = fmaf(f, mp[k], num);
            den = fmaf(f, ms[k], den);
        }
        ob[(size_t)i * D] = num / fmaxf(den, 1e-8f) + bp;
    }
}

// ---------------------------------------------------------------------------
extern "C" void kernel_launch(void* const* d_in, const int* in_sizes, int n_in,
                              void* d_out, int out_size) {
    const float* obs_emb     = (const float*)d_in[0];
    const float* obs_times   = (const float*)d_in[1];
    const float* query_times = (const float*)d_in[2];
    const float* obs_mask    = (const float*)d_in[3];
    const float* log_sigma   = (const float*)d_in[4];
    const float* W_proj      = (const float*)d_in[5];
    const float* b_proj      = (const float*)d_in[6];
    float* out = (float*)d_out;

    dim3 gA(NCH, B);
    k_moments<<<gA, 256>>>(obs_emb, obs_times, obs_mask, log_sigma);
    k_reduce_project<<<B * KT, 256>>>(W_proj);
    dim3 gC(Q / 32, B);
    k_combine<<<gC, 256>>>(query_times, log_sigma, b_proj, out);
}

// round 6
// speedup vs baseline: 11.6213x; 1.1220x over previous
#include <cuda_runtime.h>
#include <cstdint>

#define B 8
#define O 2048
#define Q 2048
#define D 128
#define KT 13      // expansion terms k = 0..12
#define NCH 64     // obs chunks per batch
#define CH 32      // obs rows per chunk

// Scratch (allocation-free rule: device globals)
__device__ __align__(16) float g_Mpart[B * NCH * KT * D];  // per-chunk moment partials
__device__ __align__(16) float g_mspart[B * NCH * KT];     // per-chunk weight-sum partials
__device__ __align__(16) float g_Mp[B * KT * D];           // projected moments
__device__ __align__(16) float g_msum[B * KT];             // weight-sum moments

__constant__ float c_invk[KT] = {0.f, 1.f, 1.f/2, 1.f/3, 1.f/4, 1.f/5, 1.f/6,
                                 1.f/7, 1.f/8, 1.f/9, 1.f/10, 1.f/11, 1.f/12};

// ---------------------------------------------------------------------------
// Kernel A: per (batch, 32-obs chunk) moment partials.
//   g_k(o) = mask_o * exp(-0.5*c2*t_o^2) * (c2*t_o)^k / k!
//   Mpart[k][e] = sum_o g_k(o)*emb[o][e] ;  mspart[k] = sum_o g_k(o)
// 512 CTAs, 256 threads. Thread (g4 = tid&31, rg = tid>>5):
//   e-range = g4*4..g4*4+3 (float4), rows = rg*4..rg*4+3. Tree-reduce 8 groups.
// ---------------------------------------------------------------------------
__global__ __launch_bounds__(256) void k_moments(
    const float* __restrict__ obs_emb,
    const float* __restrict__ obs_times,
    const float* __restrict__ obs_mask,
    const float* __restrict__ log_sigma)
{
    __shared__ __align__(16) float g_s[CH * 16];         // 13 used, padded
    __shared__ __align__(16) float red[4 * KT * D];      // 26 KB tree buffer

    const int tid = threadIdx.x;
    const int c   = blockIdx.x;
    const int b   = blockIdx.y;
    const int o0  = c * CH;
    const float c2 = expf(-2.0f * log_sigma[0]);   // 1/sigma^2

    // Phase 1: 32 threads compute g_k rows
    if (tid < CH) {
        const int o = o0 + tid;
        const float t  = obs_times[b * O + o];
        const float mk = obs_mask[b * O + o];
        const float x  = c2 * t;
        float g = mk * __expf(-0.5f * c2 * t * t);
        g_s[tid * 16 + 0] = g;
#pragma unroll
        for (int k = 1; k < KT; ++k) {
            g *= x * c_invk[k];
            g_s[tid * 16 + k] = g;
        }
    }
    __syncthreads();

    // ms partials (tiny)
    if (tid < KT) {
        float s = 0.0f;
#pragma unroll
        for (int o = 0; o < CH; ++o) s += g_s[o * 16 + tid];
        g_mspart[(b * NCH + c) * KT + tid] = s;
    }

    // Phase 2: 4 rows x 4 e-cols per thread, front-batched LDG.128 (MLP=4)
    const int g4 = tid & 31;
    const int rg = tid >> 5;
    const float* ebase = obs_emb + ((size_t)(b * O) + o0 + rg * 4) * D + g4 * 4;

    float4 x0 = *(const float4*)(ebase + 0 * D);
    float4 x1 = *(const float4*)(ebase + 1 * D);
    float4 x2 = *(const float4*)(ebase + 2 * D);
    float4 x3 = *(const float4*)(ebase + 3 * D);

    float4 acc[KT];
#pragma unroll
    for (int k = 0; k < KT; ++k) acc[k] = make_float4(0.f, 0.f, 0.f, 0.f);

    const float* gb = g_s + rg * 4 * 16;
#pragma unroll
    for (int r = 0; r < 4; ++r) {
        const float4 x = (r == 0) ? x0 : (r == 1) ? x1 : (r == 2) ? x2 : x3;
#pragma unroll
        for (int k = 0; k < KT; ++k) {
            const float g = gb[r * 16 + k];
            acc[k].x = fmaf(g, x.x, acc[k].x);
            acc[k].y = fmaf(g, x.y, acc[k].y);
            acc[k].z = fmaf(g, x.z, acc[k].z);
            acc[k].w = fmaf(g, x.w, acc[k].w);
        }
    }

    // Tree reduce 8 row-groups -> group 0
#pragma unroll
    for (int s = 4; s > 0; s >>= 1) {
        if (rg >= s && rg < 2 * s) {
            float* dst = red + (rg - s) * KT * D + g4 * 4;
#pragma unroll
            for (int k = 0; k < KT; ++k) *(float4*)(dst + k * D) = acc[k];
        }
        __syncthreads();
        if (rg < s) {
            const float* src = red + rg * KT * D + g4 * 4;
#pragma unroll
            for (int k = 0; k < KT; ++k) {
                float4 v = *(const float4*)(src + k * D);
                acc[k].x += v.x; acc[k].y += v.y; acc[k].z += v.z; acc[k].w += v.w;
            }
        }
        __syncthreads();
    }

    if (rg == 0) {
        float* dst = g_Mpart + (size_t)((b * NCH + c) * KT) * D + g4 * 4;
#pragma unroll
        for (int k = 0; k < KT; ++k) *(float4*)(dst + k * D) = acc[k];
    }
}

// ---------------------------------------------------------------------------
// Kernel B: reduce chunk partials and project through W.
// One CTA per (b, k), 512 threads: c-sum split 4-way (16 chunks each, MLP 16).
// ---------------------------------------------------------------------------
__global__ __launch_bounds__(512) void k_reduce_project(
    const float* __restrict__ W_proj)
{
    __shared__ __align__(16) float m_s[D];
    __shared__ __align__(16) float red[3 * D];
    __shared__ float msred[2];
    const int tid = threadIdx.x;
    const int e   = tid & 127;
    const int h   = tid >> 7;          // 0..3
    const int k = blockIdx.x % KT;
    const int b = blockIdx.x / KT;

    float s = 0.0f;
    const float* src = g_Mpart + (size_t)((b * NCH + h * 16) * KT + k) * D + e;
#pragma unroll 16
    for (int c = 0; c < 16; ++c)
        s += src[(size_t)c * KT * D];
    if (h > 0) red[(h - 1) * D + e] = s;

    // msum: 64 threads, one chunk each, warp-reduce
    if (tid < 64) {
        float ms = g_mspart[(b * NCH + tid) * KT + k];
#pragma unroll
        for (int off = 16; off > 0; off >>= 1)
            ms += __shfl_down_sync(0xffffffffu, ms, off);
        if ((tid & 31) == 0) msred[tid >> 5] = ms;
    }
    __syncthreads();
    if (tid == 0) g_msum[b * KT + k] = msred[0] + msred[1];
    if (h == 0) m_s[e] = s + red[e] + red[D + e] + red[2 * D + e];
    __syncthreads();

    if (h == 0) {
        // thread e = output dim: dot(W[e][:], m)
        const float4* wrow = (const float4*)(W_proj + (size_t)e * D);
        float dot = 0.0f;
#pragma unroll
        for (int i = 0; i < D / 4; ++i) {
            float4 w4 = wrow[i];
            const float4 m4 = *(const float4*)&m_s[i * 4];
            dot += w4.x * m4.x + w4.y * m4.y + w4.z * m4.z + w4.w * m4.w;
        }
        g_Mp[(size_t)(b * KT + k) * D + e] = dot;
    }
}

// ---------------------------------------------------------------------------
// Kernel C: combine. out[q][e'] = (sum_k f_k(q) Mp[k][e']) / (sum_k f_k msum[k]) + b[e']
// Mp/msum in registers. 1024 CTAs (16 q each), 256 threads, 8 q/thread.
// ---------------------------------------------------------------------------
__global__ __launch_bounds__(256) void k_combine(
    const float* __restrict__ query_times,
    const float* __restrict__ log_sigma,
    const float* __restrict__ b_proj,
    float* __restrict__ out)
{
    const int tid = threadIdx.x;
    const int b   = blockIdx.y;
    const int q0  = blockIdx.x * 16;
    const int e   = tid & 127;
    const int qh  = tid >> 7;

    float mp[KT], ms[KT];
    const float* mpb = g_Mp + (size_t)b * KT * D + e;
    const float* msb = g_msum + b * KT;
#pragma unroll
    for (int k = 0; k < KT; ++k) {
        mp[k] = mpb[k * D];
        ms[k] = msb[k];
    }

    const float c2 = expf(-2.0f * log_sigma[0]);
    const float bp = b_proj[e];
    const float* qtp = query_times + b * Q + q0 + qh * 8;
    float* ob = out + ((size_t)(b * Q) + q0 + qh * 8) * D + e;

#pragma unroll
    for (int i = 0; i < 8; ++i) {
        const float qt = qtp[i];
        float f = __expf(-0.5f * c2 * qt * qt);
        float num = f * mp[0];
        float den = f * ms[0];
#pragma unroll
        for (int k = 1; k < KT; ++k) {
            f *= qt;
            num = fmaf(f, mp[k], num);
            den = fmaf(f, ms[k], den);
        }
        ob[(size_t)i * D] = __fdividef(num, fmaxf(den, 1e-8f)) + bp;
    }
}

// ---------------------------------------------------------------------------
extern "C" void kernel_launch(void* const* d_in, const int* in_sizes, int n_in,
                              void* d_out, int out_size) {
    const float* obs_emb     = (const float*)d_in[0];
    const float* obs_times   = (const float*)d_in[1];
    const float* query_times = (const float*)d_in[2];
    const float* obs_mask    = (const float*)d_in[3];
    const float* log_sigma   = (const float*)d_in[4];
    const float* W_proj      = (const float*)d_in[5];
    const float* b_proj      = (const float*)d_in[6];
    float* out = (float*)d_out;

    dim3 gA(NCH, B);
    k_moments<<<gA, 256>>>(obs_emb, obs_times, obs_mask, log_sigma);
    k_reduce_project<<<B * KT, 512>>>(W_proj);
    dim3 gC(Q / 16, B);
    k_combine<<<gC, 256>>>(query_times, log_sigma, b_proj, out);
}

// round 7
// speedup vs baseline: 14.0051x; 1.2051x over previous
#include <cuda_runtime.h>
#include <cstdint>

#define B 8
#define O 2048
#define Q 2048
#define D 128
#define KT 13      // expansion terms k = 0..12
#define NCH 64     // obs chunks per batch
#define CH 32      // obs rows per chunk

// Scratch (allocation-free rule: device globals)
__device__ __align__(16) float g_Mpart[B * NCH * KT * D];  // per-chunk moment partials
__device__ __align__(16) float g_mspart[B * NCH * KT];     // per-chunk weight-sum partials
__device__ __align__(16) float g_Mp[B * KT * D];           // projected moments
__device__ __align__(16) float g_msum[B * KT];             // weight-sum moments

__constant__ float c_invk[KT] = {0.f, 1.f, 1.f/2, 1.f/3, 1.f/4, 1.f/5, 1.f/6,
                                 1.f/7, 1.f/8, 1.f/9, 1.f/10, 1.f/11, 1.f/12};

// ---------------------------------------------------------------------------
// Kernel A: per (batch, 32-obs chunk) moment partials.
//   g_k(o) = mask_o * exp(-0.5*c2*t_o^2) * (c2*t_o)^k / k!
//   Mpart[k][e] = sum_o g_k(o)*emb[o][e] ;  mspart[k] = sum_o g_k(o)
// 512 CTAs, 256 threads: e = tid&127, half = tid>>7 (16 rows each).
// All 16 emb loads are front-batched into registers BEFORE the g_s phase so
// DRAM latency hides under the exp chain + barrier.
// ---------------------------------------------------------------------------
__global__ __launch_bounds__(256) void k_moments(
    const float* __restrict__ obs_emb,
    const float* __restrict__ obs_times,
    const float* __restrict__ obs_mask,
    const float* __restrict__ log_sigma)
{
    __shared__ __align__(16) float g_s[CH * 16];   // 13 used, padded to 16
    __shared__ __align__(16) float red[KT * D];

    const int tid = threadIdx.x;
    const int c   = blockIdx.x;
    const int b   = blockIdx.y;
    const int o0  = c * CH;

    const int e    = tid & 127;
    const int half = tid >> 7;

    // ---- front-batched emb loads (independent of g_s) ----
    const float* ebase = obs_emb + ((size_t)(b * O) + o0 + half * 16) * D + e;
    float x[16];
#pragma unroll
    for (int oo = 0; oo < 16; ++oo) x[oo] = ebase[(size_t)oo * D];

    const float c2 = __expf(-2.0f * log_sigma[0]);   // 1/sigma^2

    // Phase 1: 32 threads compute g_k rows (overlaps with loads above)
    if (tid < CH) {
        const int o = o0 + tid;
        const float t  = obs_times[b * O + o];
        const float mk = obs_mask[b * O + o];
        const float xx = c2 * t;
        float g = mk * __expf(-0.5f * c2 * t * t);
        g_s[tid * 16 + 0] = g;
#pragma unroll
        for (int k = 1; k < KT; ++k) {
            g *= xx * c_invk[k];
            g_s[tid * 16 + k] = g;
        }
    }
    __syncthreads();

    // ms partials (tiny)
    if (tid < KT) {
        float s = 0.0f;
#pragma unroll
        for (int o = 0; o < CH; ++o) s += g_s[o * 16 + tid];
        g_mspart[(b * NCH + c) * KT + tid] = s;
    }

    // Phase 2: accumulate moments over 16 rows per thread.
    float acc[KT];
#pragma unroll
    for (int k = 0; k < KT; ++k) acc[k] = 0.0f;

    const float* gbase = g_s + half * 16 * 16;
#pragma unroll
    for (int oo = 0; oo < 16; ++oo) {
        const float xv = x[oo];
        const float4 ga = *(const float4*)(gbase + oo * 16 + 0);
        const float4 gb = *(const float4*)(gbase + oo * 16 + 4);
        const float4 gc = *(const float4*)(gbase + oo * 16 + 8);
        const float  gd = gbase[oo * 16 + 12];
        acc[0] = fmaf(ga.x, xv, acc[0]);  acc[1] = fmaf(ga.y, xv, acc[1]);
        acc[2] = fmaf(ga.z, xv, acc[2]);  acc[3] = fmaf(ga.w, xv, acc[3]);
        acc[4] = fmaf(gb.x, xv, acc[4]);  acc[5] = fmaf(gb.y, xv, acc[5]);
        acc[6] = fmaf(gb.z, xv, acc[6]);  acc[7] = fmaf(gb.w, xv, acc[7]);
        acc[8] = fmaf(gc.x, xv, acc[8]);  acc[9] = fmaf(gc.y, xv, acc[9]);
        acc[10] = fmaf(gc.z, xv, acc[10]); acc[11] = fmaf(gc.w, xv, acc[11]);
        acc[12] = fmaf(gd, xv, acc[12]);
    }

    // combine the two halves via SMEM
    if (half == 1) {
#pragma unroll
        for (int k = 0; k < KT; ++k) red[k * D + e] = acc[k];
    }
    __syncthreads();
    if (half == 0) {
        float* dst = g_Mpart + (size_t)((b * NCH + c) * KT) * D;
#pragma unroll
        for (int k = 0; k < KT; ++k) dst[k * D + e] = acc[k] + red[k * D + e];
    }
}

// ---------------------------------------------------------------------------
// Kernel B: reduce chunk partials and project through W.
// One CTA per (b, k), 512 threads: c-sum split 4-way (16 chunks each, MLP 16).
// ---------------------------------------------------------------------------
__global__ __launch_bounds__(512) void k_reduce_project(
    const float* __restrict__ W_proj)
{
    __shared__ __align__(16) float m_s[D];
    __shared__ __align__(16) float red[3 * D];
    __shared__ float msred[2];
    const int tid = threadIdx.x;
    const int e   = tid & 127;
    const int h   = tid >> 7;          // 0..3
    const int k = blockIdx.x % KT;
    const int b = blockIdx.x / KT;

    float s = 0.0f;
    const float* src = g_Mpart + (size_t)((b * NCH + h * 16) * KT + k) * D + e;
#pragma unroll 16
    for (int c = 0; c < 16; ++c)
        s += src[(size_t)c * KT * D];
    if (h > 0) red[(h - 1) * D + e] = s;

    // msum: 64 threads, one chunk each, warp-reduce
    if (tid < 64) {
        float ms = g_mspart[(b * NCH + tid) * KT + k];
#pragma unroll
        for (int off = 16; off > 0; off >>= 1)
            ms += __shfl_down_sync(0xffffffffu, ms, off);
        if ((tid & 31) == 0) msred[tid >> 5] = ms;
    }
    __syncthreads();
    if (tid == 0) g_msum[b * KT + k] = msred[0] + msred[1];
    if (h == 0) m_s[e] = s + red[e] + red[D + e] + red[2 * D + e];
    __syncthreads();

    if (h == 0) {
        // thread e = output dim: dot(W[e][:], m)
        const float4* wrow = (const float4*)(W_proj + (size_t)e * D);
        float dot = 0.0f;
#pragma unroll
        for (int i = 0; i < D / 4; ++i) {
            float4 w4 = wrow[i];
            const float4 m4 = *(const float4*)&m_s[i * 4];
            dot += w4.x * m4.x + w4.y * m4.y + w4.z * m4.z + w4.w * m4.w;
        }
        g_Mp[(size_t)(b * KT + k) * D + e] = dot;
    }
}

// ---------------------------------------------------------------------------
// Kernel C: combine. out[q][e'] = (sum_k f_k(q) Mp[k][e']) / (sum_k f_k msum[k]) + b[e']
// float4 variant: thread owns 4 e-cols (e4 = (tid&31)*4), qh = tid>>5 handles
// 2 q's. Mp/msum in registers. 1024 CTAs (16 q each), 256 threads.
// ---------------------------------------------------------------------------
__global__ __launch_bounds__(256) void k_combine(
    const float* __restrict__ query_times,
    const float* __restrict__ log_sigma,
    const float* __restrict__ b_proj,
    float* __restrict__ out)
{
    const int tid = threadIdx.x;
    const int b   = blockIdx.y;
    const int q0  = blockIdx.x * 16;
    const int e   = (tid & 31) * 4;
    const int qh  = tid >> 5;          // 0..7, 2 q's each

    float4 mp[KT];
    float  ms[KT];
    const float* mpb = g_Mp + (size_t)b * KT * D + e;
    const float* msb = g_msum + b * KT;
#pragma unroll
    for (int k = 0; k < KT; ++k) {
        mp[k] = *(const float4*)(mpb + k * D);
        ms[k] = msb[k];
    }

    const float c2 = __expf(-2.0f * log_sigma[0]);
    const float4 bp = *(const float4*)&b_proj[e];
    const float* qtp = query_times + b * Q + q0 + qh * 2;
    float* ob = out + ((size_t)(b * Q) + q0 + qh * 2) * D + e;

#pragma unroll
    for (int i = 0; i < 2; ++i) {
        const float qt = qtp[i];
        float f = __expf(-0.5f * c2 * qt * qt);
        float4 num;
        num.x = f * mp[0].x; num.y = f * mp[0].y;
        num.z = f * mp[0].z; num.w = f * mp[0].w;
        float den = f * ms[0];
#pragma unroll
        for (int k = 1; k < KT; ++k) {
            f *= qt;
            num.x = fmaf(f, mp[k].x, num.x);
            num.y = fmaf(f, mp[k].y, num.y);
            num.z = fmaf(f, mp[k].z, num.z);
            num.w = fmaf(f, mp[k].w, num.w);
            den = fmaf(f, ms[k], den);
        }
        const float inv = __fdividef(1.0f, fmaxf(den, 1e-8f));
        float4 v;
        v.x = fmaf(num.x, inv, bp.x);
        v.y = fmaf(num.y, inv, bp.y);
        v.z = fmaf(num.z, inv, bp.z);
        v.w = fmaf(num.w, inv, bp.w);
        *(float4*)(ob + (size_t)i * D) = v;
    }
}

// ---------------------------------------------------------------------------
extern "C" void kernel_launch(void* const* d_in, const int* in_sizes, int n_in,
                              void* d_out, int out_size) {
    const float* obs_emb     = (const float*)d_in[0];
    const float* obs_times   = (const float*)d_in[1];
    const float* query_times = (const float*)d_in[2];
    const float* obs_mask    = (const float*)d_in[3];
    const float* log_sigma   = (const float*)d_in[4];
    const float* W_proj      = (const float*)d_in[5];
    const float* b_proj      = (const float*)d_in[6];
    float* out = (float*)d_out;

    dim3 gA(NCH, B);
    k_moments<<<gA, 256>>>(obs_emb, obs_times, obs_mask, log_sigma);
    k_reduce_project<<<B * KT, 512>>>(W_proj);
    dim3 gC(Q / 16, B);
    k_combine<<<gC, 256>>>(query_times, log_sigma, b_proj, out);
}